// round 3
// baseline (speedup 1.0000x reference)
#include <cuda_runtime.h>

#define NN 100000
#define DD 64

// Scratch (no allocations allowed in kernel_launch)
__device__ float g_h[NN * DD];      // transformed features (x@W^T+b)
__device__ float g_a[NN * DD];      // layer-1 aggregation accumulator
__device__ int   g_deg[NN];
__device__ float g_dis[NN];         // rsqrt(deg)
__device__ float g_comb1[18 * DD];  // ebond1[t] + edir1[d], t in 0..5, d in 0..2
__device__ float g_comb2[18 * DD];

__global__ void k_deg_init(int* __restrict__ deg, int N) {
    int i = blockIdx.x * blockDim.x + threadIdx.x;
    if (i < N) deg[i] = 1;  // self-loop contributes 1 to every node's degree
}

__global__ void k_deg_count(const int* __restrict__ src, int* __restrict__ deg, int E) {
    int e = blockIdx.x * blockDim.x + threadIdx.x;
    if (e < E) atomicAdd(&deg[src[e]], 1);
}

__global__ void k_dis(const int* __restrict__ deg, float* __restrict__ dis, int N) {
    int i = blockIdx.x * blockDim.x + threadIdx.x;
    if (i < N) dis[i] = rsqrtf((float)deg[i]);
}

// comb[t*3+d][j] = ebond[t][j] + edir[d][j]
__global__ void k_comb(const float* __restrict__ eb, const float* __restrict__ ed,
                       float* __restrict__ comb) {
    int r = blockIdx.x;   // 0..17
    int j = threadIdx.x;  // 0..63
    comb[r * DD + j] = eb[(r / 3) * DD + j] + ed[(r % 3) * DD + j];
}

// Y[n][j] = sum_k act(X[n][k]) * W[j][k] + B[j]
// 256 threads, 64 rows/block; thread = (rb,q): 4 rows x 4 cols each.
__global__ __launch_bounds__(256) void k_gemm(
    const float* __restrict__ X, const float* __restrict__ W,
    const float* __restrict__ B, float* __restrict__ Y, int N, int relu) {
    __shared__ float Wt[DD][DD];   // Wt[k][j] = W[j][k]
    __shared__ float xs[64][68];   // padded: conflict-free xs[r][k] broadcast
    int tid = threadIdx.x;

    for (int i = tid; i < DD * DD; i += 256)
        Wt[i % DD][i / DD] = W[i];

    int row0 = blockIdx.x * 64;
    for (int i = tid; i < 64 * 16; i += 256) {
        int r = i >> 4, c = i & 15;
        int row = row0 + r;
        float4 v = make_float4(0.f, 0.f, 0.f, 0.f);
        if (row < N) v = ((const float4*)(X + (size_t)row * DD))[c];
        if (relu) {
            v.x = fmaxf(v.x, 0.f); v.y = fmaxf(v.y, 0.f);
            v.z = fmaxf(v.z, 0.f); v.w = fmaxf(v.w, 0.f);
        }
        *(float4*)&xs[r][c * 4] = v;
    }
    __syncthreads();

    int q = tid & 15, rb = tid >> 4;
    int j0 = q * 4;
    float4 bias = *(const float4*)(B + j0);
    float4 a0 = bias, a1 = bias, a2 = bias, a3 = bias;
    int r0 = rb * 4;

#pragma unroll
    for (int k = 0; k < DD; k++) {
        float4 w = *(const float4*)&Wt[k][j0];
        float x0 = xs[r0 + 0][k];
        float x1 = xs[r0 + 1][k];
        float x2 = xs[r0 + 2][k];
        float x3 = xs[r0 + 3][k];
        a0.x += x0 * w.x; a0.y += x0 * w.y; a0.z += x0 * w.z; a0.w += x0 * w.w;
        a1.x += x1 * w.x; a1.y += x1 * w.y; a1.z += x1 * w.z; a1.w += x1 * w.w;
        a2.x += x2 * w.x; a2.y += x2 * w.y; a2.z += x2 * w.z; a2.w += x2 * w.w;
        a3.x += x3 * w.x; a3.y += x3 * w.y; a3.z += x3 * w.z; a3.w += x3 * w.w;
    }

    int rowa = row0 + r0;
    if (rowa + 0 < N) *(float4*)(Y + (size_t)(rowa + 0) * DD + j0) = a0;
    if (rowa + 1 < N) *(float4*)(Y + (size_t)(rowa + 1) * DD + j0) = a1;
    if (rowa + 2 < N) *(float4*)(Y + (size_t)(rowa + 2) * DD + j0) = a2;
    if (rowa + 3 < N) *(float4*)(Y + (size_t)(rowa + 3) * DD + j0) = a3;
}

// Initialize accumulator with fused self-loop edge:
// out[v] = dis[v]^2 * (h[v] + comb[bt=4,bd=0])   (also initializes poisoned d_out)
__global__ __launch_bounds__(256) void k_selfinit(
    const float* __restrict__ h, const float* __restrict__ dis,
    const float* __restrict__ comb, float* __restrict__ out, int N) {
    int t = blockIdx.x * blockDim.x + threadIdx.x;
    int v = t >> 4, q = t & 15;
    if (v >= N) return;
    float nv = dis[v];
    nv *= nv;
    float4 hv = *(const float4*)(h + (size_t)v * DD + q * 4);
    float4 ev = *(const float4*)(comb + 12 * DD + q * 4);  // (4*3 + 0)
    float4 o = make_float4(nv * (hv.x + ev.x), nv * (hv.y + ev.y),
                           nv * (hv.z + ev.z), nv * (hv.w + ev.w));
    *(float4*)(out + (size_t)v * DD + q * 4) = o;
}

// Real edges: 16 threads/edge, each handles one float4 column slice.
// Gather h[src] (contiguous 256B per edge -> coalesced), vector red to out[dst].
__global__ __launch_bounds__(256) void k_edges(
    const int* __restrict__ src, const int* __restrict__ dst,
    const int* __restrict__ attr, const float* __restrict__ dis,
    const float* __restrict__ h, const float* __restrict__ comb,
    float* __restrict__ out, int E) {
    int t = blockIdx.x * blockDim.x + threadIdx.x;
    int e = t >> 4, q = t & 15;
    if (e >= E) return;
    int s  = __ldg(src + e);
    int d  = __ldg(dst + e);
    int bt = __ldg(attr + 2 * e);
    int bd = __ldg(attr + 2 * e + 1);
    float norm = __ldg(dis + s) * __ldg(dis + d);
    float4 hv = *(const float4*)(h + (size_t)s * DD + q * 4);
    float4 ev = *(const float4*)(comb + (bt * 3 + bd) * DD + q * 4);
    float mx = norm * (hv.x + ev.x);
    float my = norm * (hv.y + ev.y);
    float mz = norm * (hv.z + ev.z);
    float mw = norm * (hv.w + ev.w);
    float* p = out + (size_t)d * DD + q * 4;
    asm volatile("red.global.add.v4.f32 [%0], {%1,%2,%3,%4};"
                 :: "l"(p), "f"(mx), "f"(my), "f"(mz), "f"(mw)
                 : "memory");
}

extern "C" void kernel_launch(void* const* d_in, const int* in_sizes, int n_in,
                              void* d_out, int out_size) {
    const float* x   = (const float*)d_in[0];
    const int*   ei  = (const int*)d_in[1];
    const int*   ea  = (const int*)d_in[2];
    const float* W1  = (const float*)d_in[3];
    const float* b1  = (const float*)d_in[4];
    const float* eb1 = (const float*)d_in[5];
    const float* ed1 = (const float*)d_in[6];
    const float* W2  = (const float*)d_in[7];
    const float* b2  = (const float*)d_in[8];
    const float* eb2 = (const float*)d_in[9];
    const float* ed2 = (const float*)d_in[10];

    int N = in_sizes[0] / DD;   // 100000
    int E = in_sizes[1] / 2;    // 1000000
    const int* src = ei;
    const int* dst = ei + E;

    float *h, *a, *dis, *c1, *c2;
    int* deg;
    cudaGetSymbolAddress((void**)&h,   g_h);
    cudaGetSymbolAddress((void**)&a,   g_a);
    cudaGetSymbolAddress((void**)&deg, g_deg);
    cudaGetSymbolAddress((void**)&dis, g_dis);
    cudaGetSymbolAddress((void**)&c1,  g_comb1);
    cudaGetSymbolAddress((void**)&c2,  g_comb2);
    float* out = (float*)d_out;

    const int B = 256;
    int gN  = (N + B - 1) / B;
    int gE  = (E + B - 1) / B;
    int gNv = (N * 16 + B - 1) / B;   // 16 threads per node
    int gEv = (E * 16 + B - 1) / B;   // 16 threads per edge
    int gG  = (N + 63) / 64;

    // Degree / normalization (shared by both layers)
    k_deg_init<<<gN, B>>>(deg, N);
    k_deg_count<<<gE, B>>>(src, deg, E);
    k_dis<<<gN, B>>>(deg, dis, N);

    // Combined edge-embedding tables
    k_comb<<<18, 64>>>(eb1, ed1, c1);
    k_comb<<<18, 64>>>(eb2, ed2, c2);

    // Layer 1
    k_gemm<<<gG, 256>>>(x, W1, b1, h, N, 0);
    k_selfinit<<<gNv, B>>>(h, dis, c1, a, N);
    k_edges<<<gEv, B>>>(src, dst, ea, dis, h, c1, a, E);

    // Layer 2 (ReLU fused into GEMM input load)
    k_gemm<<<gG, 256>>>(a, W2, b2, h, N, 1);
    k_selfinit<<<gNv, B>>>(h, dis, c2, out, N);
    k_edges<<<gEv, B>>>(src, dst, ea, dis, h, c2, out, E);
}

// round 7
// speedup vs baseline: 1.2577x; 1.2577x over previous
#include <cuda_runtime.h>

#define NN 100000
#define EE 1000000
#define DD 64

// ---------------- scratch (no allocs allowed) ----------------
__device__ __align__(256) float g_h[NN * DD];   // transformed features
__device__ __align__(256) float g_a[NN * DD];   // layer-1 output
__device__ int   g_deg[NN];                     // out-degree (src) + self loop
__device__ int   g_cnt[NN];                     // in-degree (dst), real edges
__device__ int   g_cur[NN];                     // scatter cursors
__device__ int   g_excl[NN];                    // block-local exclusive scan
__device__ int   g_rowptr[NN + 1];
__device__ int   g_bsum[512];
__device__ int   g_bsumx[512];
__device__ float g_dis[NN];                     // rsqrt(deg)
__device__ float g_comb1[18 * DD];              // ebond[t]+edir[d]
__device__ float g_comb2[18 * DD];
__device__ uint2 g_rec[EE];                     // {src | combIdx<<17, norm}

// ---------------- small helpers ----------------
__device__ __forceinline__ unsigned long long fma2(unsigned long long a,
                                                   unsigned long long b,
                                                   unsigned long long c) {
    unsigned long long d;
    asm("fma.rn.f32x2 %0, %1, %2, %3;" : "=l"(d) : "l"(a), "l"(b), "l"(c));
    return d;
}
__device__ __forceinline__ unsigned long long packf2(float lo, float hi) {
    unsigned long long d;
    asm("mov.b64 %0, {%1, %2};" : "=l"(d) : "f"(lo), "f"(hi));
    return d;
}

// ---------------- prep kernels ----------------
__global__ void k_init(int* __restrict__ deg, int* __restrict__ cnt,
                       int* __restrict__ cur, int N) {
    int i = blockIdx.x * blockDim.x + threadIdx.x;
    if (i < N) { deg[i] = 1; cnt[i] = 0; cur[i] = 0; }
}

__global__ void k_hist(const int* __restrict__ src, const int* __restrict__ dst,
                       int* __restrict__ deg, int* __restrict__ cnt, int E) {
    int e = blockIdx.x * blockDim.x + threadIdx.x;
    if (e < E) {
        atomicAdd(&deg[src[e]], 1);
        atomicAdd(&cnt[dst[e]], 1);
    }
}

__global__ void k_dis(const int* __restrict__ deg, float* __restrict__ dis, int N) {
    int i = blockIdx.x * blockDim.x + threadIdx.x;
    if (i < N) dis[i] = rsqrtf((float)deg[i]);
}

__global__ void k_comb(const float* __restrict__ eb, const float* __restrict__ ed,
                       float* __restrict__ comb) {
    int r = blockIdx.x;   // 0..17
    int j = threadIdx.x;  // 0..63
    comb[r * DD + j] = eb[(r / 3) * DD + j] + ed[(r % 3) * DD + j];
}

__global__ void k_scan1(const int* __restrict__ cnt, int* __restrict__ excl,
                        int* __restrict__ bsum, int N) {
    __shared__ int s[512];
    int tid = threadIdx.x;
    int i = blockIdx.x * 512 + tid;
    int v = (i < N) ? cnt[i] : 0;
    s[tid] = v;
    __syncthreads();
    for (int off = 1; off < 512; off <<= 1) {
        int t = (tid >= off) ? s[tid - off] : 0;
        __syncthreads();
        s[tid] += t;
        __syncthreads();
    }
    if (i < N) excl[i] = s[tid] - v;
    if (tid == 511) bsum[blockIdx.x] = s[511];
}

__global__ void k_scan2(const int* __restrict__ bsum, int* __restrict__ bsumx, int NB) {
    __shared__ int s[512];
    int tid = threadIdx.x;
    int v = (tid < NB) ? bsum[tid] : 0;
    s[tid] = v;
    __syncthreads();
    for (int off = 1; off < 512; off <<= 1) {
        int t = (tid >= off) ? s[tid - off] : 0;
        __syncthreads();
        s[tid] += t;
        __syncthreads();
    }
    if (tid < NB) bsumx[tid] = s[tid] - v;
}

__global__ void k_scan3(const int* __restrict__ excl, const int* __restrict__ bsumx,
                        int* __restrict__ rowptr, int N, int E) {
    int i = blockIdx.x * blockDim.x + threadIdx.x;
    if (i < N) rowptr[i] = excl[i] + bsumx[i >> 9];
    if (i == 0) rowptr[N] = E;
}

__global__ void k_scatter(const int* __restrict__ src, const int* __restrict__ dst,
                          const int* __restrict__ attr, const float* __restrict__ dis,
                          const int* __restrict__ rowptr, int* __restrict__ cur,
                          uint2* __restrict__ rec, int E) {
    int e = blockIdx.x * blockDim.x + threadIdx.x;
    if (e >= E) return;
    int d = dst[e];
    int s = src[e];
    int2 at = ((const int2*)attr)[e];
    float nm = __ldg(dis + s) * __ldg(dis + d);
    int pos = rowptr[d] + atomicAdd(&cur[d], 1);
    rec[pos] = make_uint2((unsigned)s | ((unsigned)(at.x * 3 + at.y) << 17),
                          __float_as_uint(nm));
}

// ---------------- GEMM: Y[n][j] = sum_k act(X[n][k]) * W[j][k] + B[j] ----------------
// f32x2-packed accumulators (row pairs). Thread (q, rb): cols {q+16jj}, rows rb*4..rb*4+3.
// W staged in smem as duplicated pairs {w,w}, column-swizzled (j&48)|((j+k)&15) so
// LDS.64 reads are bank-conflict-free. Dynamic smem: 32768 (Wd) + 17408 (xs) = 50176.
__global__ __launch_bounds__(256) void k_gemm(
    const float* __restrict__ X, const float* __restrict__ W,
    const float* __restrict__ Bv, float* __restrict__ Y, int N, int relu) {
    extern __shared__ char smem[];
    unsigned long long* Wd = (unsigned long long*)smem;          // [64][64] f32x2
    float(*xs)[68] = (float(*)[68])(smem + 32768);               // [64][68]
    int tid = threadIdx.x;

    for (int i = tid; i < 4096; i += 256) {
        int k = i & 63, j = i >> 6;
        float w = W[j * 64 + k];                                 // coalesced over k
        Wd[k * 64 + ((j & 48) | ((j + k) & 15))] = packf2(w, w);
    }
    int row0 = blockIdx.x * 64;
    for (int i = tid; i < 1024; i += 256) {
        int r = i >> 4, c = i & 15;
        int row = row0 + r;
        float4 v = make_float4(0.f, 0.f, 0.f, 0.f);
        if (row < N) v = ((const float4*)(X + (size_t)row * DD))[c];
        if (relu) {
            v.x = fmaxf(v.x, 0.f); v.y = fmaxf(v.y, 0.f);
            v.z = fmaxf(v.z, 0.f); v.w = fmaxf(v.w, 0.f);
        }
        *(float4*)&xs[r][c * 4] = v;
    }
    __syncthreads();

    int q = tid & 15, rb = tid >> 4;
    int r0 = rb * 4;
    unsigned long long acc[2][4];
#pragma unroll
    for (int jj = 0; jj < 4; jj++) {
        float bj = Bv[q + 16 * jj];
        unsigned long long bb = packf2(bj, bj);
        acc[0][jj] = bb;
        acc[1][jj] = bb;
    }

#pragma unroll 16
    for (int k = 0; k < 64; k++) {
        const unsigned long long* wk = Wd + k * 64 + ((q + k) & 15);
        unsigned long long xp0 = packf2(xs[r0][k], xs[r0 + 1][k]);
        unsigned long long xp1 = packf2(xs[r0 + 2][k], xs[r0 + 3][k]);
#pragma unroll
        for (int jj = 0; jj < 4; jj++) {
            unsigned long long w = wk[16 * jj];
            acc[0][jj] = fma2(xp0, w, acc[0][jj]);
            acc[1][jj] = fma2(xp1, w, acc[1][jj]);
        }
    }

#pragma unroll
    for (int p = 0; p < 2; p++) {
#pragma unroll
        for (int rr = 0; rr < 2; rr++) {
            int row = row0 + r0 + 2 * p + rr;
            if (row < N) {
#pragma unroll
                for (int jj = 0; jj < 4; jj++) {
                    union { unsigned long long u; float2 f; } cv;
                    cv.u = acc[p][jj];
                    Y[(size_t)row * DD + q + 16 * jj] = rr ? cv.f.y : cv.f.x;
                }
            }
        }
    }
}

// ---------------- CSR aggregation (fused self-loop, single store per node) ----------------
// out[v] = dis[v]^2*(h[v]+comb[12]) + sum_{e in CSR[v]} norm_e*(h[src_e]+comb[c_e])
__global__ __launch_bounds__(256) void k_agg(
    const float* __restrict__ h, const float* __restrict__ dis,
    const float* __restrict__ comb, const int* __restrict__ rowptr,
    const uint2* __restrict__ rec, float* __restrict__ out, int N) {
    __shared__ float sc[18 * DD];
    for (int i = threadIdx.x; i < 18 * DD; i += 256) sc[i] = comb[i];
    __syncthreads();

    int t = blockIdx.x * 256 + threadIdx.x;
    int v = t >> 4, q = t & 15;
    if (v >= N) return;

    float dv = dis[v];
    float w = dv * dv;
    float4 hv = *(const float4*)(h + (size_t)v * DD + q * 4);
    const float4* esl = (const float4*)(sc + 12 * DD + q * 4);
    float4 e = *esl;
    float ax = w * (hv.x + e.x), ay = w * (hv.y + e.y);
    float az = w * (hv.z + e.z), aw = w * (hv.w + e.w);

    int i = rowptr[v], end = rowptr[v + 1];
    for (; i + 2 <= end; i += 2) {
        uint2 r0 = __ldg(&rec[i]);
        uint2 r1 = __ldg(&rec[i + 1]);
        int s0 = r0.x & 0x1FFFF, c0 = r0.x >> 17;
        int s1 = r1.x & 0x1FFFF, c1 = r1.x >> 17;
        float n0 = __uint_as_float(r0.y);
        float n1 = __uint_as_float(r1.y);
        float4 h0 = *(const float4*)(h + (size_t)s0 * DD + q * 4);
        float4 h1 = *(const float4*)(h + (size_t)s1 * DD + q * 4);
        float4 e0 = *(const float4*)(sc + c0 * DD + q * 4);
        float4 e1 = *(const float4*)(sc + c1 * DD + q * 4);
        ax += n0 * (h0.x + e0.x); ay += n0 * (h0.y + e0.y);
        az += n0 * (h0.z + e0.z); aw += n0 * (h0.w + e0.w);
        ax += n1 * (h1.x + e1.x); ay += n1 * (h1.y + e1.y);
        az += n1 * (h1.z + e1.z); aw += n1 * (h1.w + e1.w);
    }
    if (i < end) {
        uint2 r0 = __ldg(&rec[i]);
        int s0 = r0.x & 0x1FFFF, c0 = r0.x >> 17;
        float n0 = __uint_as_float(r0.y);
        float4 h0 = *(const float4*)(h + (size_t)s0 * DD + q * 4);
        float4 e0 = *(const float4*)(sc + c0 * DD + q * 4);
        ax += n0 * (h0.x + e0.x); ay += n0 * (h0.y + e0.y);
        az += n0 * (h0.z + e0.z); aw += n0 * (h0.w + e0.w);
    }
    *(float4*)(out + (size_t)v * DD + q * 4) = make_float4(ax, ay, az, aw);
}

// ---------------- launch ----------------
extern "C" void kernel_launch(void* const* d_in, const int* in_sizes, int n_in,
                              void* d_out, int out_size) {
    const float* x   = (const float*)d_in[0];
    const int*   ei  = (const int*)d_in[1];
    const int*   ea  = (const int*)d_in[2];
    const float* W1  = (const float*)d_in[3];
    const float* b1  = (const float*)d_in[4];
    const float* eb1 = (const float*)d_in[5];
    const float* ed1 = (const float*)d_in[6];
    const float* W2  = (const float*)d_in[7];
    const float* b2  = (const float*)d_in[8];
    const float* eb2 = (const float*)d_in[9];
    const float* ed2 = (const float*)d_in[10];

    int N = in_sizes[0] / DD;   // 100000
    int E = in_sizes[1] / 2;    // 1000000
    const int* src = ei;
    const int* dst = ei + E;

    float *h, *a, *dis, *c1, *c2;
    int *deg, *cnt, *cur, *rowptr, *excl, *bsum, *bsumx;
    uint2* rec;
    cudaGetSymbolAddress((void**)&h, g_h);
    cudaGetSymbolAddress((void**)&a, g_a);
    cudaGetSymbolAddress((void**)&deg, g_deg);
    cudaGetSymbolAddress((void**)&cnt, g_cnt);
    cudaGetSymbolAddress((void**)&cur, g_cur);
    cudaGetSymbolAddress((void**)&rowptr, g_rowptr);
    cudaGetSymbolAddress((void**)&excl, g_excl);
    cudaGetSymbolAddress((void**)&bsum, g_bsum);
    cudaGetSymbolAddress((void**)&bsumx, g_bsumx);
    cudaGetSymbolAddress((void**)&dis, g_dis);
    cudaGetSymbolAddress((void**)&c1, g_comb1);
    cudaGetSymbolAddress((void**)&c2, g_comb2);
    cudaGetSymbolAddress((void**)&rec, g_rec);
    float* out = (float*)d_out;

    const int B = 256;
    int gN  = (N + B - 1) / B;
    int gE  = (E + B - 1) / B;
    int gNv = (N * 16 + B - 1) / B;
    int gG  = (N + 63) / 64;
    int NB  = (N + 511) / 512;

    const int GEMM_SMEM = 32768 + 64 * 68 * 4;  // 50176
    cudaFuncSetAttribute(k_gemm, cudaFuncAttributeMaxDynamicSharedMemorySize, GEMM_SMEM);

    // degree / normalization / CSR build (shared by both layers)
    k_init<<<gN, B>>>(deg, cnt, cur, N);
    k_hist<<<gE, B>>>(src, dst, deg, cnt, E);
    k_dis<<<gN, B>>>(deg, dis, N);
    k_comb<<<18, 64>>>(eb1, ed1, c1);
    k_comb<<<18, 64>>>(eb2, ed2, c2);
    k_scan1<<<NB, 512>>>(cnt, excl, bsum, N);
    k_scan2<<<1, 512>>>(bsum, bsumx, NB);
    k_scan3<<<gN, B>>>(excl, bsumx, rowptr, N, E);
    k_scatter<<<gE, B>>>(src, dst, ea, dis, rowptr, cur, rec, E);

    // layer 1
    k_gemm<<<gG, 256, GEMM_SMEM>>>(x, W1, b1, h, N, 0);
    k_agg<<<gNv, B>>>(h, dis, c1, rowptr, rec, a, N);

    // layer 2 (ReLU fused into GEMM input load)
    k_gemm<<<gG, 256, GEMM_SMEM>>>(a, W2, b2, h, N, 1);
    k_agg<<<gNv, B>>>(h, dis, c2, rowptr, rec, out, N);
}

// round 10
// speedup vs baseline: 1.3941x; 1.1085x over previous
#include <cuda_runtime.h>

#define NN 100000
#define EE 1000000
#define DD 64

// ---------------- scratch (no allocs allowed) ----------------
__device__ __align__(256) float g_h[NN * DD];   // transformed features
__device__ __align__(256) float g_a[NN * DD];   // layer-1 output
__device__ int   g_deg[NN];                     // out-degree (src) + self loop
__device__ int   g_cnt[NN];                     // in-degree (dst), real edges
__device__ int   g_cur[NN];                     // scatter cursors (= rowptr copy)
__device__ int   g_excl[NN];                    // block-local exclusive scan
__device__ int   g_rowptr[NN + 1];
__device__ int   g_bsum[512];
__device__ float g_dis[NN];                     // rsqrt(deg)
__device__ float g_comb1[18 * DD];              // ebond[t]+edir[d]
__device__ float g_comb2[18 * DD];
__device__ uint2 g_rec[EE];                     // {src | combIdx<<17, norm}

// ---------------- small helpers ----------------
__device__ __forceinline__ unsigned long long fma2(unsigned long long a,
                                                   unsigned long long b,
                                                   unsigned long long c) {
    unsigned long long d;
    asm("fma.rn.f32x2 %0, %1, %2, %3;" : "=l"(d) : "l"(a), "l"(b), "l"(c));
    return d;
}
__device__ __forceinline__ unsigned long long packf2(float lo, float hi) {
    unsigned long long d;
    asm("mov.b64 %0, {%1, %2};" : "=l"(d) : "f"(lo), "f"(hi));
    return d;
}

// ---------------- K1: init + comb1 + comb2 (independent, fused) ----------------
__global__ void k_setup(int* __restrict__ deg, int* __restrict__ cnt,
                        const float* __restrict__ eb1, const float* __restrict__ ed1,
                        const float* __restrict__ eb2, const float* __restrict__ ed2,
                        float* __restrict__ c1, float* __restrict__ c2,
                        int N, int initBlocks) {
    int b = blockIdx.x;
    if (b < initBlocks) {
        int i = b * 256 + threadIdx.x;
        if (i < N) { deg[i] = 1; cnt[i] = 0; }
    } else if (b < initBlocks + 18) {
        int r = b - initBlocks, j = threadIdx.x;
        if (j < DD) c1[r * DD + j] = eb1[(r / 3) * DD + j] + ed1[(r % 3) * DD + j];
    } else {
        int r = b - initBlocks - 18, j = threadIdx.x;
        if (j < DD) c2[r * DD + j] = eb2[(r / 3) * DD + j] + ed2[(r % 3) * DD + j];
    }
}

// ---------------- GEMM body: Y[n][j] = sum_k act(X[n][k]) * W[j][k] + B[j] ----------
// f32x2-packed accumulators (row pairs). Thread (q, rb): cols {q+16jj}, rows rb*4..+3.
// W in smem as duplicated pairs {w,w}, column-swizzled (j&48)|((j+k)&15): LDS.64
// conflict-free. Dynamic smem: 32768 (Wd) + 17408 (xs) = 50176.
__device__ __forceinline__ void gemm_body(
    const float* __restrict__ X, const float* __restrict__ W,
    const float* __restrict__ Bv, float* __restrict__ Y, int N, int relu, int blk) {
    extern __shared__ char smem[];
    unsigned long long* Wd = (unsigned long long*)smem;          // [64][64] f32x2
    float(*xs)[68] = (float(*)[68])(smem + 32768);               // [64][68]
    int tid = threadIdx.x;

    for (int i = tid; i < 4096; i += 256) {
        int k = i & 63, j = i >> 6;
        float w = W[j * 64 + k];                                 // coalesced over k
        Wd[k * 64 + ((j & 48) | ((j + k) & 15))] = packf2(w, w);
    }
    int row0 = blk * 64;
    for (int i = tid; i < 1024; i += 256) {
        int r = i >> 4, c = i & 15;
        int row = row0 + r;
        float4 v = make_float4(0.f, 0.f, 0.f, 0.f);
        if (row < N) v = ((const float4*)(X + (size_t)row * DD))[c];
        if (relu) {
            v.x = fmaxf(v.x, 0.f); v.y = fmaxf(v.y, 0.f);
            v.z = fmaxf(v.z, 0.f); v.w = fmaxf(v.w, 0.f);
        }
        *(float4*)&xs[r][c * 4] = v;
    }
    __syncthreads();

    int q = tid & 15, rb = tid >> 4;
    int r0 = rb * 4;
    unsigned long long acc[2][4];
#pragma unroll
    for (int jj = 0; jj < 4; jj++) {
        float bj = Bv[q + 16 * jj];
        unsigned long long bb = packf2(bj, bj);
        acc[0][jj] = bb;
        acc[1][jj] = bb;
    }

#pragma unroll 16
    for (int k = 0; k < 64; k++) {
        const unsigned long long* wk = Wd + k * 64 + ((q + k) & 15);
        unsigned long long xp0 = packf2(xs[r0][k], xs[r0 + 1][k]);
        unsigned long long xp1 = packf2(xs[r0 + 2][k], xs[r0 + 3][k]);
#pragma unroll
        for (int jj = 0; jj < 4; jj++) {
            unsigned long long w = wk[16 * jj];
            acc[0][jj] = fma2(xp0, w, acc[0][jj]);
            acc[1][jj] = fma2(xp1, w, acc[1][jj]);
        }
    }

#pragma unroll
    for (int p = 0; p < 2; p++) {
#pragma unroll
        for (int rr = 0; rr < 2; rr++) {
            int row = row0 + r0 + 2 * p + rr;
            if (row < N) {
#pragma unroll
                for (int jj = 0; jj < 4; jj++) {
                    union { unsigned long long u; float2 f; } cv;
                    cv.u = acc[p][jj];
                    Y[(size_t)row * DD + q + 16 * jj] = rr ? cv.f.y : cv.f.x;
                }
            }
        }
    }
}

// ---------------- K2/K7: GEMM blocks + (optional) histogram blocks ----------------
__global__ __launch_bounds__(256) void k_gemm_hist(
    const float* __restrict__ X, const float* __restrict__ W,
    const float* __restrict__ Bv, float* __restrict__ Y, int N, int relu,
    const int* __restrict__ src, const int* __restrict__ dst,
    int* __restrict__ deg, int* __restrict__ cnt, int E, int gemmBlocks) {
    if ((int)blockIdx.x < gemmBlocks) {
        gemm_body(X, W, Bv, Y, N, relu, blockIdx.x);
    } else if (E > 0) {
        int idx = (blockIdx.x - gemmBlocks) * 256 + threadIdx.x;
        int stride = (gridDim.x - gemmBlocks) * 256;
        for (int e = idx; e < E; e += stride) {
            atomicAdd(&deg[src[e]], 1);
            atomicAdd(&cnt[dst[e]], 1);
        }
    }
}

// ---------------- K3: block-local scan of cnt + dis = rsqrt(deg) ----------------
__global__ void k_scan1_dis(const int* __restrict__ cnt, const int* __restrict__ deg,
                            int* __restrict__ excl, int* __restrict__ bsum,
                            float* __restrict__ dis, int N) {
    __shared__ int s[512];
    int tid = threadIdx.x;
    int i = blockIdx.x * 512 + tid;
    int v = (i < N) ? cnt[i] : 0;
    s[tid] = v;
    __syncthreads();
    for (int off = 1; off < 512; off <<= 1) {
        int t = (tid >= off) ? s[tid - off] : 0;
        __syncthreads();
        s[tid] += t;
        __syncthreads();
    }
    if (i < N) {
        excl[i] = s[tid] - v;
        dis[i] = rsqrtf((float)deg[i]);
    }
    if (tid == 511) bsum[blockIdx.x] = s[511];
}

// ---------------- K4: per-block prefix of bsum + final rowptr + cursor copy -------
__global__ void k_scan23(const int* __restrict__ excl, const int* __restrict__ bsum,
                         int* __restrict__ rowptr, int* __restrict__ cur,
                         int N, int E, int NB) {
    __shared__ int warpsum[16];
    __shared__ int prefix_s;
    int b = blockIdx.x, t = threadIdx.x;
    int v = (t < b && t < NB) ? bsum[t] : 0;
#pragma unroll
    for (int o = 16; o; o >>= 1) v += __shfl_down_sync(0xFFFFFFFFu, v, o);
    if ((t & 31) == 0) warpsum[t >> 5] = v;
    __syncthreads();
    if (t == 0) {
        int s = 0;
#pragma unroll
        for (int w = 0; w < 16; w++) s += warpsum[w];
        prefix_s = s;
    }
    __syncthreads();
    int prefix = prefix_s;
    int i = b * 512 + t;
    if (i < N) {
        int r = excl[i] + prefix;
        rowptr[i] = r;
        cur[i] = r;
    }
    if (b == 0 && t == 0) rowptr[N] = E;
}

// ---------------- K5: scatter packed edge records into CSR slots ----------------
__global__ void k_scatter(const int* __restrict__ src, const int* __restrict__ dst,
                          const int* __restrict__ attr, const float* __restrict__ dis,
                          int* __restrict__ cur, uint2* __restrict__ rec, int E) {
    int e = blockIdx.x * blockDim.x + threadIdx.x;
    if (e >= E) return;
    int d = dst[e];
    int s = src[e];
    int2 at = ((const int2*)attr)[e];
    float nm = __ldg(dis + s) * __ldg(dis + d);
    int pos = atomicAdd(&cur[d], 1);
    rec[pos] = make_uint2((unsigned)s | ((unsigned)(at.x * 3 + at.y) << 17),
                          __float_as_uint(nm));
}

// ---------------- K6/K8: CSR aggregation, 4 edges/iter, fused self-loop ----------
// out[v] = dis[v]^2*(h[v]+comb[12]) + sum_{e in CSR[v]} norm_e*(h[src_e]+comb[c_e])
__global__ __launch_bounds__(256) void k_agg(
    const float* __restrict__ h, const float* __restrict__ dis,
    const float* __restrict__ comb, const int* __restrict__ rowptr,
    const uint2* __restrict__ rec, float* __restrict__ out, int N) {
    __shared__ float sc[18 * DD];
    for (int i = threadIdx.x; i < 18 * DD; i += 256) sc[i] = comb[i];
    __syncthreads();

    int t = blockIdx.x * 256 + threadIdx.x;
    int v = t >> 4, q = t & 15;
    if (v >= N) return;

    float dv = dis[v];
    float w = dv * dv;
    float4 hv = *(const float4*)(h + (size_t)v * DD + q * 4);
    float4 e = *(const float4*)(sc + 12 * DD + q * 4);
    float ax = w * (hv.x + e.x), ay = w * (hv.y + e.y);
    float az = w * (hv.z + e.z), aw = w * (hv.w + e.w);

    int i = rowptr[v], end = rowptr[v + 1];
    for (; i + 4 <= end; i += 4) {
        uint2 r0 = __ldg(&rec[i]);
        uint2 r1 = __ldg(&rec[i + 1]);
        uint2 r2 = __ldg(&rec[i + 2]);
        uint2 r3 = __ldg(&rec[i + 3]);
        const float4* p0 = (const float4*)(h + (size_t)(r0.x & 0x1FFFF) * DD + q * 4);
        const float4* p1 = (const float4*)(h + (size_t)(r1.x & 0x1FFFF) * DD + q * 4);
        const float4* p2 = (const float4*)(h + (size_t)(r2.x & 0x1FFFF) * DD + q * 4);
        const float4* p3 = (const float4*)(h + (size_t)(r3.x & 0x1FFFF) * DD + q * 4);
        float4 h0 = *p0, h1 = *p1, h2 = *p2, h3 = *p3;
        float4 e0 = *(const float4*)(sc + (r0.x >> 17) * DD + q * 4);
        float4 e1 = *(const float4*)(sc + (r1.x >> 17) * DD + q * 4);
        float4 e2 = *(const float4*)(sc + (r2.x >> 17) * DD + q * 4);
        float4 e3 = *(const float4*)(sc + (r3.x >> 17) * DD + q * 4);
        float n0 = __uint_as_float(r0.y), n1 = __uint_as_float(r1.y);
        float n2 = __uint_as_float(r2.y), n3 = __uint_as_float(r3.y);
        ax += n0 * (h0.x + e0.x); ay += n0 * (h0.y + e0.y);
        az += n0 * (h0.z + e0.z); aw += n0 * (h0.w + e0.w);
        ax += n1 * (h1.x + e1.x); ay += n1 * (h1.y + e1.y);
        az += n1 * (h1.z + e1.z); aw += n1 * (h1.w + e1.w);
        ax += n2 * (h2.x + e2.x); ay += n2 * (h2.y + e2.y);
        az += n2 * (h2.z + e2.z); aw += n2 * (h2.w + e2.w);
        ax += n3 * (h3.x + e3.x); ay += n3 * (h3.y + e3.y);
        az += n3 * (h3.z + e3.z); aw += n3 * (h3.w + e3.w);
    }
    for (; i < end; i++) {
        uint2 r0 = __ldg(&rec[i]);
        float n0 = __uint_as_float(r0.y);
        float4 h0 = *(const float4*)(h + (size_t)(r0.x & 0x1FFFF) * DD + q * 4);
        float4 e0 = *(const float4*)(sc + (r0.x >> 17) * DD + q * 4);
        ax += n0 * (h0.x + e0.x); ay += n0 * (h0.y + e0.y);
        az += n0 * (h0.z + e0.z); aw += n0 * (h0.w + e0.w);
    }
    *(float4*)(out + (size_t)v * DD + q * 4) = make_float4(ax, ay, az, aw);
}

// ---------------- launch ----------------
extern "C" void kernel_launch(void* const* d_in, const int* in_sizes, int n_in,
                              void* d_out, int out_size) {
    const float* x   = (const float*)d_in[0];
    const int*   ei  = (const int*)d_in[1];
    const int*   ea  = (const int*)d_in[2];
    const float* W1  = (const float*)d_in[3];
    const float* b1  = (const float*)d_in[4];
    const float* eb1 = (const float*)d_in[5];
    const float* ed1 = (const float*)d_in[6];
    const float* W2  = (const float*)d_in[7];
    const float* b2  = (const float*)d_in[8];
    const float* eb2 = (const float*)d_in[9];
    const float* ed2 = (const float*)d_in[10];

    int N = in_sizes[0] / DD;   // 100000
    int E = in_sizes[1] / 2;    // 1000000
    const int* src = ei;
    const int* dst = ei + E;

    float *h, *a, *dis, *c1, *c2;
    int *deg, *cnt, *cur, *rowptr, *excl, *bsum;
    uint2* rec;
    cudaGetSymbolAddress((void**)&h, g_h);
    cudaGetSymbolAddress((void**)&a, g_a);
    cudaGetSymbolAddress((void**)&deg, g_deg);
    cudaGetSymbolAddress((void**)&cnt, g_cnt);
    cudaGetSymbolAddress((void**)&cur, g_cur);
    cudaGetSymbolAddress((void**)&rowptr, g_rowptr);
    cudaGetSymbolAddress((void**)&excl, g_excl);
    cudaGetSymbolAddress((void**)&bsum, g_bsum);
    cudaGetSymbolAddress((void**)&dis, g_dis);
    cudaGetSymbolAddress((void**)&c1, g_comb1);
    cudaGetSymbolAddress((void**)&c2, g_comb2);
    cudaGetSymbolAddress((void**)&rec, g_rec);
    float* out = (float*)d_out;

    const int B = 256;
    int gN  = (N + B - 1) / B;          // init blocks
    int gE  = (E + B - 1) / B;
    int gNv = (N * 16 + B - 1) / B;
    int gG  = (N + 63) / 64;            // gemm blocks
    int NB  = (N + 511) / 512;          // scan blocks
    const int HB = 1024;                // hist blocks riding alongside GEMM1

    const int GEMM_SMEM = 32768 + 64 * 68 * 4;  // 50176
    cudaFuncSetAttribute(k_gemm_hist, cudaFuncAttributeMaxDynamicSharedMemorySize,
                         GEMM_SMEM);

    // K1: init + both comb tables
    k_setup<<<gN + 36, B>>>(deg, cnt, eb1, ed1, eb2, ed2, c1, c2, N, gN);
    // K2: GEMM layer 1 overlapped with degree histogram
    k_gemm_hist<<<gG + HB, B, GEMM_SMEM>>>(x, W1, b1, h, N, 0,
                                           src, dst, deg, cnt, E, gG);
    // K3: block scan of cnt + dis
    k_scan1_dis<<<NB, 512>>>(cnt, deg, excl, bsum, dis, N);
    // K4: finalize rowptr + cursors
    k_scan23<<<NB, 512>>>(excl, bsum, rowptr, cur, N, E, NB);
    // K5: scatter edge records
    k_scatter<<<gE, B>>>(src, dst, ea, dis, cur, rec, E);
    // K6: layer-1 aggregation
    k_agg<<<gNv, B>>>(h, dis, c1, rowptr, rec, a, N);
    // K7: GEMM layer 2 (ReLU fused into input load), no hist blocks
    k_gemm_hist<<<gG, B, GEMM_SMEM>>>(a, W2, b2, h, N, 1,
                                      src, dst, deg, cnt, 0, gG);
    // K8: layer-2 aggregation -> output
    k_agg<<<gNv, B>>>(h, dis, c2, rowptr, rec, out, N);
}